// round 15
// baseline (speedup 1.0000x reference)
#include <cuda_runtime.h>
#include <cuda_bf16.h>
#include <math.h>
#include <stdint.h>

#define NGv 12
#define Bv  8
#define Sv  1280
#define Cv  512
#define BSv (Bv * Sv)

typedef __nv_bfloat16 bf16;

// ---------------- device scratch ----------------
__device__ bf16  g_xh [Bv*Sv*Cv], g_xl [Bv*Sv*Cv];
__device__ bf16  g_xth[Bv*Cv*Sv], g_xtl[Bv*Cv*Sv];
__device__ bf16  g_wth[NGv*Cv*Cv], g_wtl[NGv*Cv*Cv];
__device__ bf16  g_wph[NGv*Cv*Cv], g_wpl[NGv*Cv*Cv];
__device__ bf16  g_wgh[NGv*Cv*Cv], g_wgl[NGv*Cv*Cv];
__device__ bf16  g_thh[2*Bv*Sv*Cv], g_thl[2*Bv*Sv*Cv];   // theta double-buffered (set = i&1)
__device__ bf16  g_phh[2*Bv*Sv*Cv], g_phl[2*Bv*Sv*Cv];   // phi double-buffered
__device__ float g_sim[Bv*Sv*Sv];
__device__ bf16  g_ath[Bv*Sv*Sv], g_atl[Bv*Sv*Sv];
__device__ bf16  g_tph[2*Bv*Sv*Cv], g_tpl[2*Bv*Sv*Cv];   // tmp double-buffered (set = i&1)
__device__ float g_agg[Bv*Sv*Cv];
__device__ float g_cx[Bv*Sv], g_cy[Bv*Sv], g_rr[Bv*Sv];
__device__ double g_stats[NGv*Bv*2];

// ---------------- helpers ----------------
__device__ __forceinline__ uint32_t sm2u(const void* p) {
    uint32_t a;
    asm("{ .reg .u64 t; cvta.to.shared.u64 t, %1; cvt.u32.u64 %0, t; }" : "=r"(a) : "l"(p));
    return a;
}
// SW64 swizzle: 64B rows, atom = 8 rows x 64B (proven in R11)
#define SWZ64(o) ((o) ^ (((o) >> 3) & 0x30u))

__device__ __forceinline__ void bsplit(float x, bf16& h, bf16& l) {
    h = __float2bfloat16(x);
    l = __float2bfloat16(x - __bfloat162float(h));
}

__device__ __forceinline__ void cpasync16(uint32_t dst, const void* src) {
    asm volatile("cp.async.cg.shared.global [%0], [%1], 16;" :: "r"(dst), "l"(src));
}
// .noinc is load-bearing (R4 deadlock otherwise).
__device__ __forceinline__ void cpasync_arrive_noinc(uint32_t bar) {
    asm volatile("cp.async.mbarrier.arrive.noinc.shared.b64 [%0];" :: "r"(bar));
}
__device__ __forceinline__ void mbar_init(uint32_t bar, uint32_t cnt) {
    asm volatile("mbarrier.init.shared.b64 [%0], %1;" :: "r"(bar), "r"(cnt) : "memory");
}
__device__ __forceinline__ void mbar_wait(uint32_t bar, uint32_t parity) {
    asm volatile(
        "{\n\t"
        ".reg .pred P;\n\t"
        "WL%=:\n\t"
        "mbarrier.try_wait.parity.acquire.cta.shared::cta.b64 P, [%0], %1;\n\t"
        "@P bra WD%=;\n\t"
        "bra WL%=;\n\t"
        "WD%=:\n\t"
        "}"
        :: "r"(bar), "r"(parity) : "memory");
}
__device__ __forceinline__ void fence_proxy_async_cta() {
    asm volatile("fence.proxy.async.shared::cta;" ::: "memory");
}
__device__ __forceinline__ void kahan(float& s, float& c, float v) {
    float y = v - c;
    float t = s + y;
    c = (t - s) - y;
    s = t;
}

#if defined(__CUDA_ARCH_FEAT_SM103_ALL) || !defined(__CUDA_ARCH__)
#define HAS_TCGEN05 1
#else
#define HAS_TCGEN05 0
#endif

#if HAS_TCGEN05
__device__ __forceinline__ void tc_commit(uint32_t bar) {
    asm volatile("tcgen05.commit.cta_group::1.mbarrier::arrive::one.shared::cluster.b64 [%0];"
                 :: "r"(bar) : "memory");
}
__device__ __forceinline__ void mma_bf16(uint32_t d, uint64_t ad, uint64_t bd, uint32_t idesc, bool acc) {
    uint32_t e = acc ? 1u : 0u;
    asm volatile(
        "{\n\t"
        ".reg .pred p;\n\t"
        "setp.ne.u32 p, %4, 0;\n\t"
        "tcgen05.mma.cta_group::1.kind::f16 [%0], %1, %2, %3, p;\n\t"
        "}"
        :: "r"(d), "l"(ad), "l"(bd), "r"(idesc), "r"(e) : "memory");
}
#define TC_ALLOC(smemaddr, n) \
    asm volatile("tcgen05.alloc.cta_group::1.sync.aligned.shared::cta.b32 [%0], %1;" \
                 :: "r"(smemaddr), "r"((uint32_t)(n)) : "memory")
#define TC_RELINQ() \
    asm volatile("tcgen05.relinquish_alloc_permit.cta_group::1.sync.aligned;")
#define TC_DEALLOC(tm, n) \
    asm volatile("tcgen05.dealloc.cta_group::1.sync.aligned.b32 %0, %1;" :: "r"(tm), "r"((uint32_t)(n)))
#define TC_FENCE_AFTER()  asm volatile("tcgen05.fence::after_thread_sync;" ::: "memory")
#define TC_WAIT_LD()      asm volatile("tcgen05.wait::ld.sync.aligned;" ::: "memory")
#define LDTM32(r, a) \
    asm volatile( \
        "tcgen05.ld.sync.aligned.32x32b.x32.b32 " \
        "{%0, %1, %2, %3, %4, %5, %6, %7, " \
        " %8, %9, %10, %11, %12, %13, %14, %15, " \
        " %16, %17, %18, %19, %20, %21, %22, %23, " \
        " %24, %25, %26, %27, %28, %29, %30, %31}, [%32];" \
        : "=r"((r)[0]),  "=r"((r)[1]),  "=r"((r)[2]),  "=r"((r)[3]), \
          "=r"((r)[4]),  "=r"((r)[5]),  "=r"((r)[6]),  "=r"((r)[7]), \
          "=r"((r)[8]),  "=r"((r)[9]),  "=r"((r)[10]), "=r"((r)[11]), \
          "=r"((r)[12]), "=r"((r)[13]), "=r"((r)[14]), "=r"((r)[15]), \
          "=r"((r)[16]), "=r"((r)[17]), "=r"((r)[18]), "=r"((r)[19]), \
          "=r"((r)[20]), "=r"((r)[21]), "=r"((r)[22]), "=r"((r)[23]), \
          "=r"((r)[24]), "=r"((r)[25]), "=r"((r)[26]), "=r"((r)[27]), \
          "=r"((r)[28]), "=r"((r)[29]), "=r"((r)[30]), "=r"((r)[31]) \
        : "r"(a))
#endif

// SW64 descriptor: layout=4, version=1 (Blackwell), SBO=32 (8 rows x 64B /16), LBO=1
static constexpr uint64_t DESC_BASE_SW64 =
    (4ull << 61) | (1ull << 46) | (32ull << 32) | (1ull << 16);
__device__ __forceinline__ uint64_t mk_desc(uint32_t addr) {
    return DESC_BASE_SW64 | ((uint64_t)(addr >> 4) & 0x3FFFull);
}

// idesc (kind::f16): dtype=F32, atype=BF16, btype=BF16, N=256, M=128
static constexpr uint32_t IDESC_BF = (1u << 4) | (1u << 7) | (1u << 10) | (32u << 17) | (8u << 24);

// ---------------- tcgen05 3xBF16 GEMM (R11-proven): D = alpha*(A @ B^T) + bias -------
// KC=32 (64B rows, SW64), stage 48KB, 2 stages = 96KB -> 2 CTAs/SM.
#define KC 32
#define OFF_AL 8192
#define OFF_BH 16384
#define OFF_BL 32768
#define STG_BYTES 49152
#define DYN_BYTES 98304

__global__ __launch_bounds__(160, 2)
void tcgemm(const bf16* __restrict__ Ah, const bf16* __restrict__ Al, size_t sAz, int ldA,
            const bf16* __restrict__ Bh, const bf16* __restrict__ Bl,
            const bf16* __restrict__ Bh2, const bf16* __restrict__ Bl2, size_t sBz, int ldB,
            float* outF, bf16* outH, bf16* outL, bf16* outH2, bf16* outL2,
            size_t sOz, int ldO,
            const float* bias, const float* bias2, float alpha, int K, int zsplit,
            double* statsBase)
{
    int z = blockIdx.z;
    if (z >= zsplit) { z -= zsplit; Bh = Bh2; Bl = Bl2; outH = outH2; outL = outL2; bias = bias2; }
    const int m0   = blockIdx.y * 128;
    const int col0 = blockIdx.x * 256;

#if HAS_TCGEN05
    extern __shared__ __align__(1024) char dynsm[];
    __shared__ __align__(8) uint64_t s_full[2], s_empty[2], s_done;
    __shared__ uint32_t s_tptr;
    __shared__ float s_red[8];

    const int tid = threadIdx.x;
    const int wid = tid >> 5;
    const int lane = tid & 31;

    const uint32_t dynu = sm2u(dynsm);
    uint32_t fullb[2]  = { sm2u(&s_full[0]),  sm2u(&s_full[1])  };
    uint32_t emptyb[2] = { sm2u(&s_empty[0]), sm2u(&s_empty[1]) };
    const uint32_t doneb = sm2u(&s_done);

    if (tid == 0) {
        mbar_init(fullb[0], 128); mbar_init(fullb[1], 128);
        mbar_init(emptyb[0], 1);  mbar_init(emptyb[1], 1);
        mbar_init(doneb, 1);
    }
    __syncthreads();
    if (wid == 4) {
        TC_ALLOC(sm2u(&s_tptr), 256);
        TC_RELINQ();
    }
    __syncthreads();
    const uint32_t tmem = s_tptr;

    const int nk = K / KC;

    if (wid < 4) {
        // ---- producers (128 threads); rows are 64B (KC=32 bf16) ----
        const bf16* aH = Ah + (size_t)z * sAz + (size_t)m0 * ldA;
        const bf16* aL = Al + (size_t)z * sAz + (size_t)m0 * ldA;
        const bf16* bH = Bh + (size_t)z * sBz + (size_t)col0 * ldB;
        const bf16* bL = Bl + (size_t)z * sBz + (size_t)col0 * ldB;
        int st = 0, ph = 1;
        for (int c = 0; c < nk; c++) {
            mbar_wait(emptyb[st], ph);
            const uint32_t sb = dynu + st * STG_BYTES;
            const int k0 = c * KC;
            #pragma unroll
            for (int i = 0; i < 4; i++) {
                int idx = i * 128 + tid;
                int r = idx >> 2, cc = idx & 3;
                uint32_t so = SWZ64((uint32_t)(r * 64 + cc * 16));
                const size_t go = (size_t)r * ldA + k0 + cc * 8;
                cpasync16(sb + so, aH + go);
                cpasync16(sb + OFF_AL + so, aL + go);
            }
            #pragma unroll
            for (int i = 0; i < 8; i++) {
                int idx = i * 128 + tid;
                int r = idx >> 2, cc = idx & 3;
                uint32_t so = SWZ64((uint32_t)(r * 64 + cc * 16));
                const size_t go = (size_t)r * ldB + k0 + cc * 8;
                cpasync16(sb + OFF_BH + so, bH + go);
                cpasync16(sb + OFF_BL + so, bL + go);
            }
            cpasync_arrive_noinc(fullb[st]);
            if (++st == 2) { st = 0; ph ^= 1; }
        }
    } else if (lane == 0) {
        // ---- MMA issuer: 2 K-steps (16 bf16 each) x {hh, hl, lh} per chunk ----
        int st = 0, ph = 0;
        for (int c = 0; c < nk; c++) {
            mbar_wait(fullb[st], ph);
            fence_proxy_async_cta();
            const uint32_t sb = dynu + st * STG_BYTES;
            uint64_t dah = mk_desc(sb),          dal = mk_desc(sb + OFF_AL);
            uint64_t dbh = mk_desc(sb + OFF_BH), dbl = mk_desc(sb + OFF_BL);
            #pragma unroll
            for (int ks = 0; ks < 2; ks++)
                mma_bf16(tmem, dah + ks * 2, dbh + ks * 2, IDESC_BF, !(c == 0 && ks == 0));
            #pragma unroll
            for (int ks = 0; ks < 2; ks++)
                mma_bf16(tmem, dah + ks * 2, dbl + ks * 2, IDESC_BF, true);
            #pragma unroll
            for (int ks = 0; ks < 2; ks++)
                mma_bf16(tmem, dal + ks * 2, dbh + ks * 2, IDESC_BF, true);
            tc_commit(emptyb[st]);
            if (++st == 2) { st = 0; ph ^= 1; }
        }
        tc_commit(doneb);
    }

    mbar_wait(doneb, 0);
    TC_FENCE_AFTER();

    const bool dostats = (statsBase != nullptr);
    float sacc = 0.f, sc = 0.f, qacc = 0.f, qc = 0.f;

    if (wid < 4) {
        float* tile = (float*)(dynsm + wid * 4352);     // 32x33 floats per warp
        const size_t obase = (size_t)z * sOz;
        for (int c0 = 0; c0 < 256; c0 += 32) {
            uint32_t regs[32];
            LDTM32(regs, tmem + c0);
            TC_WAIT_LD();
            #pragma unroll
            for (int j = 0; j < 32; j++) {
                float v = __uint_as_float(regs[j]) * alpha;
                if (bias) v += bias[col0 + c0 + j];
                tile[lane * 33 + j] = v;
                if (dostats) { kahan(sacc, sc, v); kahan(qacc, qc, v * v); }
            }
            __syncwarp();
            #pragma unroll
            for (int i = 0; i < 8; i++) {
                int f = i * 32 + lane;
                int rr = f >> 3, q = (f & 7) * 4;
                float vv[4];
                vv[0] = tile[rr * 33 + q + 0];
                vv[1] = tile[rr * 33 + q + 1];
                vv[2] = tile[rr * 33 + q + 2];
                vv[3] = tile[rr * 33 + q + 3];
                size_t off = obase + (size_t)(m0 + wid * 32 + rr) * ldO + col0 + c0 + q;
                if (outF) {
                    float4 o4 = { vv[0], vv[1], vv[2], vv[3] };
                    *(float4*)(outF + off) = o4;
                }
                if (outH) {
                    uint32_t hw[4], lw[4];
                    #pragma unroll
                    for (int t = 0; t < 4; t++) {
                        bf16 h, l;
                        bsplit(vv[t], h, l);
                        hw[t] = (uint32_t)__bfloat16_as_ushort(h);
                        lw[t] = (uint32_t)__bfloat16_as_ushort(l);
                    }
                    uint2 uh = { hw[0] | (hw[1] << 16), hw[2] | (hw[3] << 16) };
                    uint2 ul = { lw[0] | (lw[1] << 16), lw[2] | (lw[3] << 16) };
                    *(uint2*)(outH + off) = uh;
                    *(uint2*)(outL + off) = ul;
                }
            }
            __syncwarp();
        }
        if (dostats) {
            #pragma unroll
            for (int o = 16; o > 0; o >>= 1) {
                sacc += __shfl_xor_sync(0xffffffffu, sacc, o);
                qacc += __shfl_xor_sync(0xffffffffu, qacc, o);
            }
            if (lane == 0) { s_red[wid] = sacc; s_red[4 + wid] = qacc; }
        }
    }
    __syncthreads();
    if (dostats && tid == 0) {
        double s = (double)s_red[0] + s_red[1] + s_red[2] + s_red[3];
        double q = (double)s_red[4] + s_red[5] + s_red[6] + s_red[7];
        atomicAdd(&statsBase[z * 2 + 0], s);
        atomicAdd(&statsBase[z * 2 + 1], q);
    }
    if (wid == 4) TC_DEALLOC(tmem, 256);
#else
    // -------- plain-sm_103 fallback (insurance; never the selected cubin) --------
    const bf16* aH = Ah + (size_t)z * sAz;
    const bf16* aL = Al + (size_t)z * sAz;
    const bf16* bH = Bh + (size_t)z * sBz;
    const bf16* bL = Bl + (size_t)z * sBz;
    for (int idx = threadIdx.x; idx < 128 * 256; idx += blockDim.x) {
        int mi = m0 + (idx >> 8);
        int ni = col0 + (idx & 255);
        const bf16* pa  = aH + (size_t)mi * ldA;
        const bf16* pa2 = aL + (size_t)mi * ldA;
        const bf16* pb  = bH + (size_t)ni * ldB;
        const bf16* pb2 = bL + (size_t)ni * ldB;
        float s = 0.f;
        for (int k = 0; k < K; k++)
            s += (__bfloat162float(pa[k]) + __bfloat162float(pa2[k])) *
                 (__bfloat162float(pb[k]) + __bfloat162float(pb2[k]));
        float v = s * alpha + (bias ? bias[ni] : 0.f);
        size_t off = (size_t)z * sOz + (size_t)mi * ldO + ni;
        if (outF) outF[off] = v;
        if (outH) {
            bf16 h, l;
            bsplit(v, h, l);
            outH[off] = h;
            outL[off] = l;
        }
        if (statsBase) {
            atomicAdd(&statsBase[z * 2 + 0], (double)v);
            atomicAdd(&statsBase[z * 2 + 1], (double)v * (double)v);
        }
    }
#endif
}

// ---------------- x: straight split + transposed split ----------
__global__ void conv_x_kernel(const float* __restrict__ in, bf16* __restrict__ th,
                              bf16* __restrict__ tl, bf16* __restrict__ sh,
                              bf16* __restrict__ sl)
{
    __shared__ float t[32][33];
    const int z = blockIdx.z;
    const size_t zb = (size_t)z * Sv * Cv;
    const int r0 = blockIdx.y * 32, c0 = blockIdx.x * 32;
    #pragma unroll
    for (int k = 0; k < 4; k++) {
        int r = r0 + threadIdx.y + k * 8;
        size_t idx = zb + (size_t)r * Cv + c0 + threadIdx.x;
        float v = in[idx];
        t[threadIdx.y + k * 8][threadIdx.x] = v;
        bf16 h, l;
        bsplit(v, h, l);
        sh[idx] = h;
        sl[idx] = l;
    }
    __syncthreads();
    #pragma unroll
    for (int k = 0; k < 4; k++) {
        int cc = c0 + threadIdx.y + k * 8;
        int rr = r0 + threadIdx.x;
        float v = t[threadIdx.x][threadIdx.y + k * 8];
        size_t o = zb + (size_t)cc * Sv + rr;
        bf16 h, l;
        bsplit(v, h, l);
        th[o] = h;
        tl[o] = l;
    }
}

// ---------------- all weights: transposed split in ONE launch (z = 3*NG) -------------
__global__ void conv_w_kernel(const float* __restrict__ Wt, const float* __restrict__ Wp,
                              const float* __restrict__ Wg,
                              bf16* __restrict__ wth, bf16* __restrict__ wtl,
                              bf16* __restrict__ wph, bf16* __restrict__ wpl,
                              bf16* __restrict__ wgh, bf16* __restrict__ wgl)
{
    __shared__ float t[32][33];
    const int z = blockIdx.z;
    const int w = z / NGv, i = z % NGv;
    const float* in = (w == 0 ? Wt : (w == 1 ? Wp : Wg));
    bf16* th = (w == 0 ? wth : (w == 1 ? wph : wgh));
    bf16* tl = (w == 0 ? wtl : (w == 1 ? wpl : wgl));
    const size_t zb = (size_t)i * Cv * Cv;
    const int r0 = blockIdx.y * 32, c0 = blockIdx.x * 32;
    #pragma unroll
    for (int k = 0; k < 4; k++) {
        int r = r0 + threadIdx.y + k * 8;
        t[threadIdx.y + k * 8][threadIdx.x] = in[zb + (size_t)r * Cv + c0 + threadIdx.x];
    }
    __syncthreads();
    #pragma unroll
    for (int k = 0; k < 4; k++) {
        int cc = c0 + threadIdx.y + k * 8;
        int rr = r0 + threadIdx.x;
        float v = t[threadIdx.x][threadIdx.y + k * 8];
        size_t o = zb + (size_t)cc * Cv + rr;
        bf16 h, l;
        bsplit(v, h, l);
        th[o] = h;
        tl[o] = l;
    }
}

// ---------------- box centers + zero LN stats ----------------
__global__ void pos_kernel(const float* __restrict__ box)
{
    int idx = blockIdx.x * blockDim.x + threadIdx.x;
    if (blockIdx.x == 0 && threadIdx.x < NGv * Bv * 2) g_stats[threadIdx.x] = 0.0;
    if (idx >= Bv * Sv) return;
    float cx = (box[idx * 4 + 0] + box[idx * 4 + 2]) * 0.5f;
    float cy = (box[idx * 4 + 1] + box[idx * 4 + 3]) * 0.5f;
    g_cx[idx] = cx; g_cy[idx] = cy; g_rr[idx] = cx * cx + cy * cy;
}

// ---------------- masked softmax -> bf16 hi/lo (+optional fp32 relation_graph) --------
__global__ __launch_bounds__(256)
void masked_softmax_kernel(const float* __restrict__ sim, bf16* __restrict__ aH,
                           bf16* __restrict__ aL, float* relF, const void* __restrict__ owp)
{
    const int row = blockIdx.x;
    const int b = row / Sv;
    const int tid = threadIdx.x;
    const float* srow = sim + (size_t)row * Sv;

    float ow = 224.0f;
    if (owp) {
        int vi = *(const int*)owp;
        ow = (vi > 0 && vi < 1000000) ? (float)vi : __int_as_float(vi);
    }
    const float thr2 = (0.2f * ow) * (0.2f * ow);

    const float rn = g_rr[row], cxn = g_cx[row], cyn = g_cy[row];
    const float* cxb = g_cx + b * Sv;
    const float* cyb = g_cy + b * Sv;
    const float* rb  = g_rr + b * Sv;

    float v[5];
    float mx = -INFINITY;
    #pragma unroll
    for (int u = 0; u < 5; u++) {
        int m = tid + u * 256;
        float d2 = (rn - 2.0f * (cxn * cxb[m] + cyn * cyb[m])) + rb[m];
        v[u] = (d2 > thr2) ? -INFINITY : srow[m];
        mx = fmaxf(mx, v[u]);
    }

    __shared__ float sh[8];
    #pragma unroll
    for (int o = 16; o > 0; o >>= 1) mx = fmaxf(mx, __shfl_xor_sync(0xffffffffu, mx, o));
    if ((tid & 31) == 0) sh[tid >> 5] = mx;
    __syncthreads();
    if (tid < 32) {
        float t = (tid < 8) ? sh[tid] : -INFINITY;
        #pragma unroll
        for (int o = 4; o > 0; o >>= 1) t = fmaxf(t, __shfl_xor_sync(0xffffffffu, t, o));
        if (tid == 0) sh[0] = t;
    }
    __syncthreads();
    mx = sh[0];
    __syncthreads();

    float sum = 0.f;
    #pragma unroll
    for (int u = 0; u < 5; u++) { v[u] = __expf(v[u] - mx); sum += v[u]; }
    #pragma unroll
    for (int o = 16; o > 0; o >>= 1) sum += __shfl_xor_sync(0xffffffffu, sum, o);
    if ((tid & 31) == 0) sh[tid >> 5] = sum;
    __syncthreads();
    if (tid < 32) {
        float t = (tid < 8) ? sh[tid] : 0.f;
        #pragma unroll
        for (int o = 4; o > 0; o >>= 1) t += __shfl_xor_sync(0xffffffffu, t, o);
        if (tid == 0) sh[0] = t;
    }
    __syncthreads();
    const float inv = 1.0f / sh[0];
    #pragma unroll
    for (int u = 0; u < 5; u++) {
        size_t o = (size_t)row * Sv + tid + u * 256;
        float p = v[u] * inv;
        bf16 h, l;
        bsplit(p, h, l);
        aH[o] = h;
        aL[o] = l;
        if (relF) relF[o] = p;
    }
}

// -------- finalize: out (+)= relu(LN(agg)*scale + bias), mu/rstd inline from stats ----
__global__ __launch_bounds__(256)
void finalize_kernel(const float* __restrict__ agg, const float* __restrict__ lns,
                     const float* __restrict__ lnb, float* __restrict__ out,
                     int first, const double* __restrict__ st)
{
    const size_t SC = (size_t)Sv * Cv;
    size_t idx = (size_t)blockIdx.x * blockDim.x + threadIdx.x;
    if (idx >= (size_t)Bv * SC) return;
    int b = (int)(idx / SC);
    int j = (int)(idx % SC);
    __shared__ float smu, srstd;
    if (threadIdx.x == 0) {
        const double n = (double)Sv * (double)Cv;
        double mu = st[b * 2 + 0] / n;
        double var = st[b * 2 + 1] / n - mu * mu;
        smu = (float)mu;
        srstd = rsqrtf((float)var + 1e-5f);
    }
    __syncthreads();
    float v = (agg[idx] - smu) * srstd * lns[j] + lnb[j];
    v = fmaxf(v, 0.f);
    out[idx] = first ? v : out[idx] + v;
}

// ---------------- launch ----------------
extern "C" void kernel_launch(void* const* d_in, const int* in_sizes, int n_in,
                              void* d_out, int out_size)
{
    const float* x   = (const float*)d_in[0];
    const float* box = (const float*)d_in[1];
    const float* Wt  = (const float*)d_in[2];
    const float* bt  = (const float*)d_in[3];
    const float* Wp  = (const float*)d_in[4];
    const float* bp  = (const float*)d_in[5];
    const float* Wg  = (const float*)d_in[6];
    const float* lns = (const float*)d_in[7];
    const float* lnb = (const float*)d_in[8];
    const void*  owp = (n_in > 10) ? d_in[10] : nullptr;

    float* out = (float*)d_out;
    float* rel = out + (size_t)Bv * Sv * Cv;

    bf16 *xh, *xl, *xth, *xtl, *wth, *wtl, *wph, *wpl, *wgh, *wgl;
    bf16 *thh, *thl, *phh, *phl, *ath, *atl, *tph, *tpl;
    float *sim, *agg;
    double *stats;
    cudaGetSymbolAddress((void**)&xh,  g_xh);  cudaGetSymbolAddress((void**)&xl,  g_xl);
    cudaGetSymbolAddress((void**)&xth, g_xth); cudaGetSymbolAddress((void**)&xtl, g_xtl);
    cudaGetSymbolAddress((void**)&wth, g_wth); cudaGetSymbolAddress((void**)&wtl, g_wtl);
    cudaGetSymbolAddress((void**)&wph, g_wph); cudaGetSymbolAddress((void**)&wpl, g_wpl);
    cudaGetSymbolAddress((void**)&wgh, g_wgh); cudaGetSymbolAddress((void**)&wgl, g_wgl);
    cudaGetSymbolAddress((void**)&thh, g_thh); cudaGetSymbolAddress((void**)&thl, g_thl);
    cudaGetSymbolAddress((void**)&phh, g_phh); cudaGetSymbolAddress((void**)&phl, g_phl);
    cudaGetSymbolAddress((void**)&sim, g_sim);
    cudaGetSymbolAddress((void**)&ath, g_ath); cudaGetSymbolAddress((void**)&atl, g_atl);
    cudaGetSymbolAddress((void**)&tph, g_tph); cudaGetSymbolAddress((void**)&tpl, g_tpl);
    cudaGetSymbolAddress((void**)&agg, g_agg);
    cudaGetSymbolAddress((void**)&stats, g_stats);

    cudaFuncSetAttribute(tcgemm, cudaFuncAttributeMaxDynamicSharedMemorySize, DYN_BYTES);

    const size_t sSC = (size_t)Sv * Cv;
    const size_t sSS = (size_t)Sv * Sv;
    const size_t sCC = (size_t)Cv * Cv;
    const size_t sCS = (size_t)Cv * Sv;
    const float inv_sqrt = 0.04419417382415922f;
    const int NOSPLIT = 1 << 30;

    // stream B: theta/phi prefetch AND agg+finalize epilogue (both off the critical path)
    cudaStream_t sB;
    cudaStreamCreateWithFlags(&sB, cudaStreamNonBlocking);
    cudaEvent_t evFork, evJoin, evT[NGv], evS[NGv], evM[NGv], evA[NGv];
    cudaEventCreateWithFlags(&evFork, cudaEventDisableTiming);
    cudaEventCreateWithFlags(&evJoin, cudaEventDisableTiming);
    for (int i = 0; i < NGv; i++) {
        cudaEventCreateWithFlags(&evT[i], cudaEventDisableTiming);
        cudaEventCreateWithFlags(&evS[i], cudaEventDisableTiming);
        cudaEventCreateWithFlags(&evM[i], cudaEventDisableTiming);
        cudaEventCreateWithFlags(&evA[i], cudaEventDisableTiming);
    }

    pos_kernel<<<(Bv * Sv + 255) / 256, 256>>>(box);
    conv_x_kernel<<<dim3(Cv / 32, Sv / 32, Bv), dim3(32, 8)>>>(x, xth, xtl, xh, xl);
    conv_w_kernel<<<dim3(Cv / 32, Cv / 32, 3 * NGv), dim3(32, 8)>>>(
        Wt, Wp, Wg, wth, wtl, wph, wpl, wgh, wgl);

    cudaEventRecord(evFork, 0);
    cudaStreamWaitEvent(sB, evFork, 0);

    for (int i = 0; i < NGv; i++) {
        const int set = i & 1;
        bf16* thhS = thh + (size_t)set * Bv * sSC;
        bf16* thlS = thl + (size_t)set * Bv * sSC;
        bf16* phhS = phh + (size_t)set * Bv * sSC;
        bf16* phlS = phl + (size_t)set * Bv * sSC;
        bf16* tphS = tph + (size_t)set * Bv * sSC;
        bf16* tplS = tpl + (size_t)set * Bv * sSC;

        // ---- stream B: theta & phi for subgraph i (waits sim(i-2) = last reader of set)
        if (i >= 2) cudaStreamWaitEvent(sB, evS[i - 2], 0);
        tcgemm<<<dim3(2, 10, 16), 160, DYN_BYTES, sB>>>(
            xh, xl, sSC, Cv,
            wth + i * sCC, wtl + i * sCC, wph + i * sCC, wpl + i * sCC, 0, Cv,
            nullptr, thhS, thlS, phhS, phlS, sSC, Cv,
            bt + (size_t)i * Cv, bp + (size_t)i * Cv, 1.0f, Cv, 8, nullptr);
        cudaEventRecord(evT[i], sB);

        // ---- main stream: sim -> softmax -> tmp ----
        cudaStreamWaitEvent(0, evT[i], 0);
        tcgemm<<<dim3(5, 10, 8), 160, DYN_BYTES>>>(
            thhS, thlS, sSC, Cv,
            phhS, phlS, nullptr, nullptr, sSC, Cv,
            sim, nullptr, nullptr, nullptr, nullptr, sSS, Sv,
            nullptr, nullptr, inv_sqrt, Cv, NOSPLIT, nullptr);
        cudaEventRecord(evS[i], 0);

        masked_softmax_kernel<<<Bv * Sv, 256>>>(sim, ath, atl, (i == NGv - 1) ? rel : nullptr, owp);

        // tmp(i) writes tph[set]; agg(i-2) was the last reader of that set
        if (i >= 2) cudaStreamWaitEvent(0, evA[i - 2], 0);
        tcgemm<<<dim3(2, 10, 8), 160, DYN_BYTES>>>(
            ath, atl, sSS, Sv,
            xth, xtl, nullptr, nullptr, sCS, Sv,
            nullptr, tphS, tplS, nullptr, nullptr, sSC, Cv,
            nullptr, nullptr, 1.0f, Sv, NOSPLIT, nullptr);
        cudaEventRecord(evM[i], 0);

        // ---- stream B: agg + finalize (off critical path; serial in i on B) ----
        cudaStreamWaitEvent(sB, evM[i], 0);
        tcgemm<<<dim3(2, 10, 8), 160, DYN_BYTES, sB>>>(
            tphS, tplS, sSC, Cv,
            wgh + i * sCC, wgl + i * sCC, nullptr, nullptr, 0, Cv,
            agg, nullptr, nullptr, nullptr, nullptr, sSC, Cv,
            nullptr, nullptr, 1.0f, Cv, NOSPLIT, stats + (size_t)i * Bv * 2);

        finalize_kernel<<<(int)((sSC * Bv + 255) / 256), 256, 0, sB>>>(
            agg, lns + (size_t)i * sSC, lnb + (size_t)i * sSC, out,
            i == 0 ? 1 : 0, stats + (size_t)i * Bv * 2);
        cudaEventRecord(evA[i], sB);
    }

    // join stream B back to the origin stream (required: last writes to `out` are on B)
    cudaStreamWaitEvent(0, evA[NGv - 1], 0);

    cudaEventDestroy(evFork);
    cudaEventDestroy(evJoin);
    for (int i = 0; i < NGv; i++) {
        cudaEventDestroy(evT[i]); cudaEventDestroy(evS[i]);
        cudaEventDestroy(evM[i]); cudaEventDestroy(evA[i]);
    }
    cudaStreamDestroy(sB);
}

// round 16
// speedup vs baseline: 1.2241x; 1.2241x over previous
#include <cuda_runtime.h>
#include <cuda_bf16.h>
#include <math.h>
#include <stdint.h>

#define NGv 12
#define Bv  8
#define Sv  1280
#define Cv  512
#define BSv (Bv * Sv)

typedef __nv_bfloat16 bf16;

// ---------------- device scratch ----------------
__device__ bf16  g_xh [Bv*Sv*Cv], g_xl [Bv*Sv*Cv];
__device__ bf16  g_xth[Bv*Cv*Sv], g_xtl[Bv*Cv*Sv];
__device__ bf16  g_wth[NGv*Cv*Cv], g_wtl[NGv*Cv*Cv];
__device__ bf16  g_wph[NGv*Cv*Cv], g_wpl[NGv*Cv*Cv];
__device__ bf16  g_wgh[NGv*Cv*Cv], g_wgl[NGv*Cv*Cv];
__device__ bf16  g_thh[2*Bv*Sv*Cv], g_thl[2*Bv*Sv*Cv];   // theta double-buffered (set = i&1)
__device__ bf16  g_phh[2*Bv*Sv*Cv], g_phl[2*Bv*Sv*Cv];   // phi double-buffered
__device__ float g_sim[Bv*Sv*Sv];
__device__ bf16  g_ath[Bv*Sv*Sv], g_atl[Bv*Sv*Sv];
__device__ bf16  g_tph[2*Bv*Sv*Cv], g_tpl[2*Bv*Sv*Cv];   // tmp double-buffered (set = i&1)
__device__ float g_agg[Bv*Sv*Cv];
__device__ float g_cx[Bv*Sv], g_cy[Bv*Sv], g_rr[Bv*Sv];
__device__ double g_stats[NGv*Bv*2];

// ---------------- helpers ----------------
__device__ __forceinline__ uint32_t sm2u(const void* p) {
    uint32_t a;
    asm("{ .reg .u64 t; cvta.to.shared.u64 t, %1; cvt.u32.u64 %0, t; }" : "=r"(a) : "l"(p));
    return a;
}
// SW64 swizzle: 64B rows, atom = 8 rows x 64B (proven in R11)
#define SWZ64(o) ((o) ^ (((o) >> 3) & 0x30u))

__device__ __forceinline__ void bsplit(float x, bf16& h, bf16& l) {
    h = __float2bfloat16(x);
    l = __float2bfloat16(x - __bfloat162float(h));
}

__device__ __forceinline__ void cpasync16(uint32_t dst, const void* src) {
    asm volatile("cp.async.cg.shared.global [%0], [%1], 16;" :: "r"(dst), "l"(src));
}
// .noinc is load-bearing (R4 deadlock otherwise).
__device__ __forceinline__ void cpasync_arrive_noinc(uint32_t bar) {
    asm volatile("cp.async.mbarrier.arrive.noinc.shared.b64 [%0];" :: "r"(bar));
}
__device__ __forceinline__ void mbar_init(uint32_t bar, uint32_t cnt) {
    asm volatile("mbarrier.init.shared.b64 [%0], %1;" :: "r"(bar), "r"(cnt) : "memory");
}
__device__ __forceinline__ void mbar_wait(uint32_t bar, uint32_t parity) {
    asm volatile(
        "{\n\t"
        ".reg .pred P;\n\t"
        "WL%=:\n\t"
        "mbarrier.try_wait.parity.acquire.cta.shared::cta.b64 P, [%0], %1;\n\t"
        "@P bra WD%=;\n\t"
        "bra WL%=;\n\t"
        "WD%=:\n\t"
        "}"
        :: "r"(bar), "r"(parity) : "memory");
}
__device__ __forceinline__ void fence_proxy_async_cta() {
    asm volatile("fence.proxy.async.shared::cta;" ::: "memory");
}
__device__ __forceinline__ void kahan(float& s, float& c, float v) {
    float y = v - c;
    float t = s + y;
    c = (t - s) - y;
    s = t;
}

#if defined(__CUDA_ARCH_FEAT_SM103_ALL) || !defined(__CUDA_ARCH__)
#define HAS_TCGEN05 1
#else
#define HAS_TCGEN05 0
#endif

#if HAS_TCGEN05
__device__ __forceinline__ void tc_commit(uint32_t bar) {
    asm volatile("tcgen05.commit.cta_group::1.mbarrier::arrive::one.shared::cluster.b64 [%0];"
                 :: "r"(bar) : "memory");
}
__device__ __forceinline__ void mma_bf16(uint32_t d, uint64_t ad, uint64_t bd, uint32_t idesc, bool acc) {
    uint32_t e = acc ? 1u : 0u;
    asm volatile(
        "{\n\t"
        ".reg .pred p;\n\t"
        "setp.ne.u32 p, %4, 0;\n\t"
        "tcgen05.mma.cta_group::1.kind::f16 [%0], %1, %2, %3, p;\n\t"
        "}"
        :: "r"(d), "l"(ad), "l"(bd), "r"(idesc), "r"(e) : "memory");
}
#define TC_ALLOC(smemaddr, n) \
    asm volatile("tcgen05.alloc.cta_group::1.sync.aligned.shared::cta.b32 [%0], %1;" \
                 :: "r"(smemaddr), "r"((uint32_t)(n)) : "memory")
#define TC_RELINQ() \
    asm volatile("tcgen05.relinquish_alloc_permit.cta_group::1.sync.aligned;")
#define TC_DEALLOC(tm, n) \
    asm volatile("tcgen05.dealloc.cta_group::1.sync.aligned.b32 %0, %1;" :: "r"(tm), "r"((uint32_t)(n)))
#define TC_FENCE_AFTER()  asm volatile("tcgen05.fence::after_thread_sync;" ::: "memory")
#define TC_WAIT_LD()      asm volatile("tcgen05.wait::ld.sync.aligned;" ::: "memory")
#define LDTM32(r, a) \
    asm volatile( \
        "tcgen05.ld.sync.aligned.32x32b.x32.b32 " \
        "{%0, %1, %2, %3, %4, %5, %6, %7, " \
        " %8, %9, %10, %11, %12, %13, %14, %15, " \
        " %16, %17, %18, %19, %20, %21, %22, %23, " \
        " %24, %25, %26, %27, %28, %29, %30, %31}, [%32];" \
        : "=r"((r)[0]),  "=r"((r)[1]),  "=r"((r)[2]),  "=r"((r)[3]), \
          "=r"((r)[4]),  "=r"((r)[5]),  "=r"((r)[6]),  "=r"((r)[7]), \
          "=r"((r)[8]),  "=r"((r)[9]),  "=r"((r)[10]), "=r"((r)[11]), \
          "=r"((r)[12]), "=r"((r)[13]), "=r"((r)[14]), "=r"((r)[15]), \
          "=r"((r)[16]), "=r"((r)[17]), "=r"((r)[18]), "=r"((r)[19]), \
          "=r"((r)[20]), "=r"((r)[21]), "=r"((r)[22]), "=r"((r)[23]), \
          "=r"((r)[24]), "=r"((r)[25]), "=r"((r)[26]), "=r"((r)[27]), \
          "=r"((r)[28]), "=r"((r)[29]), "=r"((r)[30]), "=r"((r)[31]) \
        : "r"(a))
#endif

// SW64 descriptor: layout=4, version=1 (Blackwell), SBO=32 (8 rows x 64B /16), LBO=1
static constexpr uint64_t DESC_BASE_SW64 =
    (4ull << 61) | (1ull << 46) | (32ull << 32) | (1ull << 16);
__device__ __forceinline__ uint64_t mk_desc(uint32_t addr) {
    return DESC_BASE_SW64 | ((uint64_t)(addr >> 4) & 0x3FFFull);
}

// idesc (kind::f16): dtype=F32, atype=BF16, btype=BF16, N=256, M=128
static constexpr uint32_t IDESC_BF = (1u << 4) | (1u << 7) | (1u << 10) | (32u << 17) | (8u << 24);

// ---------------- tcgen05 3xBF16 GEMM (R11-proven): D = alpha*(A @ B^T) + bias -------
// KC=32 (64B rows, SW64), stage 48KB, 2 stages = 96KB -> 2 CTAs/SM.
#define KC 32
#define OFF_AL 8192
#define OFF_BH 16384
#define OFF_BL 32768
#define STG_BYTES 49152
#define DYN_BYTES 98304

__global__ __launch_bounds__(160, 2)
void tcgemm(const bf16* __restrict__ Ah, const bf16* __restrict__ Al, size_t sAz, int ldA,
            const bf16* __restrict__ Bh, const bf16* __restrict__ Bl,
            const bf16* __restrict__ Bh2, const bf16* __restrict__ Bl2, size_t sBz, int ldB,
            float* outF, bf16* outH, bf16* outL, bf16* outH2, bf16* outL2,
            size_t sOz, int ldO,
            const float* bias, const float* bias2, float alpha, int K, int zsplit,
            double* statsBase)
{
    int z = blockIdx.z;
    if (z >= zsplit) { z -= zsplit; Bh = Bh2; Bl = Bl2; outH = outH2; outL = outL2; bias = bias2; }
    const int m0   = blockIdx.y * 128;
    const int col0 = blockIdx.x * 256;

#if HAS_TCGEN05
    extern __shared__ __align__(1024) char dynsm[];
    __shared__ __align__(8) uint64_t s_full[2], s_empty[2], s_done;
    __shared__ uint32_t s_tptr;
    __shared__ float s_red[8];

    const int tid = threadIdx.x;
    const int wid = tid >> 5;
    const int lane = tid & 31;

    const uint32_t dynu = sm2u(dynsm);
    uint32_t fullb[2]  = { sm2u(&s_full[0]),  sm2u(&s_full[1])  };
    uint32_t emptyb[2] = { sm2u(&s_empty[0]), sm2u(&s_empty[1]) };
    const uint32_t doneb = sm2u(&s_done);

    if (tid == 0) {
        mbar_init(fullb[0], 128); mbar_init(fullb[1], 128);
        mbar_init(emptyb[0], 1);  mbar_init(emptyb[1], 1);
        mbar_init(doneb, 1);
    }
    __syncthreads();
    if (wid == 4) {
        TC_ALLOC(sm2u(&s_tptr), 256);
        TC_RELINQ();
    }
    __syncthreads();
    const uint32_t tmem = s_tptr;

    const int nk = K / KC;

    if (wid < 4) {
        // ---- producers (128 threads); rows are 64B (KC=32 bf16) ----
        const bf16* aH = Ah + (size_t)z * sAz + (size_t)m0 * ldA;
        const bf16* aL = Al + (size_t)z * sAz + (size_t)m0 * ldA;
        const bf16* bH = Bh + (size_t)z * sBz + (size_t)col0 * ldB;
        const bf16* bL = Bl + (size_t)z * sBz + (size_t)col0 * ldB;
        int st = 0, ph = 1;
        for (int c = 0; c < nk; c++) {
            mbar_wait(emptyb[st], ph);
            const uint32_t sb = dynu + st * STG_BYTES;
            const int k0 = c * KC;
            #pragma unroll
            for (int i = 0; i < 4; i++) {
                int idx = i * 128 + tid;
                int r = idx >> 2, cc = idx & 3;
                uint32_t so = SWZ64((uint32_t)(r * 64 + cc * 16));
                const size_t go = (size_t)r * ldA + k0 + cc * 8;
                cpasync16(sb + so, aH + go);
                cpasync16(sb + OFF_AL + so, aL + go);
            }
            #pragma unroll
            for (int i = 0; i < 8; i++) {
                int idx = i * 128 + tid;
                int r = idx >> 2, cc = idx & 3;
                uint32_t so = SWZ64((uint32_t)(r * 64 + cc * 16));
                const size_t go = (size_t)r * ldB + k0 + cc * 8;
                cpasync16(sb + OFF_BH + so, bH + go);
                cpasync16(sb + OFF_BL + so, bL + go);
            }
            cpasync_arrive_noinc(fullb[st]);
            if (++st == 2) { st = 0; ph ^= 1; }
        }
    } else if (lane == 0) {
        // ---- MMA issuer: 2 K-steps (16 bf16 each) x {hh, hl, lh} per chunk ----
        int st = 0, ph = 0;
        for (int c = 0; c < nk; c++) {
            mbar_wait(fullb[st], ph);
            fence_proxy_async_cta();
            const uint32_t sb = dynu + st * STG_BYTES;
            uint64_t dah = mk_desc(sb),          dal = mk_desc(sb + OFF_AL);
            uint64_t dbh = mk_desc(sb + OFF_BH), dbl = mk_desc(sb + OFF_BL);
            #pragma unroll
            for (int ks = 0; ks < 2; ks++)
                mma_bf16(tmem, dah + ks * 2, dbh + ks * 2, IDESC_BF, !(c == 0 && ks == 0));
            #pragma unroll
            for (int ks = 0; ks < 2; ks++)
                mma_bf16(tmem, dah + ks * 2, dbl + ks * 2, IDESC_BF, true);
            #pragma unroll
            for (int ks = 0; ks < 2; ks++)
                mma_bf16(tmem, dal + ks * 2, dbh + ks * 2, IDESC_BF, true);
            tc_commit(emptyb[st]);
            if (++st == 2) { st = 0; ph ^= 1; }
        }
        tc_commit(doneb);
    }

    mbar_wait(doneb, 0);
    TC_FENCE_AFTER();

    const bool dostats = (statsBase != nullptr);
    float sacc = 0.f, sc = 0.f, qacc = 0.f, qc = 0.f;

    if (wid < 4) {
        float* tile = (float*)(dynsm + wid * 4352);     // 32x33 floats per warp
        const size_t obase = (size_t)z * sOz;
        for (int c0 = 0; c0 < 256; c0 += 32) {
            uint32_t regs[32];
            LDTM32(regs, tmem + c0);
            TC_WAIT_LD();
            #pragma unroll
            for (int j = 0; j < 32; j++) {
                float v = __uint_as_float(regs[j]) * alpha;
                if (bias) v += bias[col0 + c0 + j];
                tile[lane * 33 + j] = v;
                if (dostats) { kahan(sacc, sc, v); kahan(qacc, qc, v * v); }
            }
            __syncwarp();
            #pragma unroll
            for (int i = 0; i < 8; i++) {
                int f = i * 32 + lane;
                int rr = f >> 3, q = (f & 7) * 4;
                float vv[4];
                vv[0] = tile[rr * 33 + q + 0];
                vv[1] = tile[rr * 33 + q + 1];
                vv[2] = tile[rr * 33 + q + 2];
                vv[3] = tile[rr * 33 + q + 3];
                size_t off = obase + (size_t)(m0 + wid * 32 + rr) * ldO + col0 + c0 + q;
                if (outF) {
                    float4 o4 = { vv[0], vv[1], vv[2], vv[3] };
                    *(float4*)(outF + off) = o4;
                }
                if (outH) {
                    uint32_t hw[4], lw[4];
                    #pragma unroll
                    for (int t = 0; t < 4; t++) {
                        bf16 h, l;
                        bsplit(vv[t], h, l);
                        hw[t] = (uint32_t)__bfloat16_as_ushort(h);
                        lw[t] = (uint32_t)__bfloat16_as_ushort(l);
                    }
                    uint2 uh = { hw[0] | (hw[1] << 16), hw[2] | (hw[3] << 16) };
                    uint2 ul = { lw[0] | (lw[1] << 16), lw[2] | (lw[3] << 16) };
                    *(uint2*)(outH + off) = uh;
                    *(uint2*)(outL + off) = ul;
                }
            }
            __syncwarp();
        }
        if (dostats) {
            #pragma unroll
            for (int o = 16; o > 0; o >>= 1) {
                sacc += __shfl_xor_sync(0xffffffffu, sacc, o);
                qacc += __shfl_xor_sync(0xffffffffu, qacc, o);
            }
            if (lane == 0) { s_red[wid] = sacc; s_red[4 + wid] = qacc; }
        }
    }
    __syncthreads();
    if (dostats && tid == 0) {
        double s = (double)s_red[0] + s_red[1] + s_red[2] + s_red[3];
        double q = (double)s_red[4] + s_red[5] + s_red[6] + s_red[7];
        atomicAdd(&statsBase[z * 2 + 0], s);
        atomicAdd(&statsBase[z * 2 + 1], q);
    }
    if (wid == 4) TC_DEALLOC(tmem, 256);
#else
    // -------- plain-sm_103 fallback (insurance; never the selected cubin) --------
    const bf16* aH = Ah + (size_t)z * sAz;
    const bf16* aL = Al + (size_t)z * sAz;
    const bf16* bH = Bh + (size_t)z * sBz;
    const bf16* bL = Bl + (size_t)z * sBz;
    for (int idx = threadIdx.x; idx < 128 * 256; idx += blockDim.x) {
        int mi = m0 + (idx >> 8);
        int ni = col0 + (idx & 255);
        const bf16* pa  = aH + (size_t)mi * ldA;
        const bf16* pa2 = aL + (size_t)mi * ldA;
        const bf16* pb  = bH + (size_t)ni * ldB;
        const bf16* pb2 = bL + (size_t)ni * ldB;
        float s = 0.f;
        for (int k = 0; k < K; k++)
            s += (__bfloat162float(pa[k]) + __bfloat162float(pa2[k])) *
                 (__bfloat162float(pb[k]) + __bfloat162float(pb2[k]));
        float v = s * alpha + (bias ? bias[ni] : 0.f);
        size_t off = (size_t)z * sOz + (size_t)mi * ldO + ni;
        if (outF) outF[off] = v;
        if (outH) {
            bf16 h, l;
            bsplit(v, h, l);
            outH[off] = h;
            outL[off] = l;
        }
        if (statsBase) {
            atomicAdd(&statsBase[z * 2 + 0], (double)v);
            atomicAdd(&statsBase[z * 2 + 1], (double)v * (double)v);
        }
    }
#endif
}

// ---------------- x: straight split + transposed split ----------
__global__ void conv_x_kernel(const float* __restrict__ in, bf16* __restrict__ th,
                              bf16* __restrict__ tl, bf16* __restrict__ sh,
                              bf16* __restrict__ sl)
{
    __shared__ float t[32][33];
    const int z = blockIdx.z;
    const size_t zb = (size_t)z * Sv * Cv;
    const int r0 = blockIdx.y * 32, c0 = blockIdx.x * 32;
    #pragma unroll
    for (int k = 0; k < 4; k++) {
        int r = r0 + threadIdx.y + k * 8;
        size_t idx = zb + (size_t)r * Cv + c0 + threadIdx.x;
        float v = in[idx];
        t[threadIdx.y + k * 8][threadIdx.x] = v;
        bf16 h, l;
        bsplit(v, h, l);
        sh[idx] = h;
        sl[idx] = l;
    }
    __syncthreads();
    #pragma unroll
    for (int k = 0; k < 4; k++) {
        int cc = c0 + threadIdx.y + k * 8;
        int rr = r0 + threadIdx.x;
        float v = t[threadIdx.x][threadIdx.y + k * 8];
        size_t o = zb + (size_t)cc * Sv + rr;
        bf16 h, l;
        bsplit(v, h, l);
        th[o] = h;
        tl[o] = l;
    }
}

// ---------------- all weights: transposed split in ONE launch (z = 3*NG) -------------
__global__ void conv_w_kernel(const float* __restrict__ Wt, const float* __restrict__ Wp,
                              const float* __restrict__ Wg,
                              bf16* __restrict__ wth, bf16* __restrict__ wtl,
                              bf16* __restrict__ wph, bf16* __restrict__ wpl,
                              bf16* __restrict__ wgh, bf16* __restrict__ wgl)
{
    __shared__ float t[32][33];
    const int z = blockIdx.z;
    const int w = z / NGv, i = z % NGv;
    const float* in = (w == 0 ? Wt : (w == 1 ? Wp : Wg));
    bf16* th = (w == 0 ? wth : (w == 1 ? wph : wgh));
    bf16* tl = (w == 0 ? wtl : (w == 1 ? wpl : wgl));
    const size_t zb = (size_t)i * Cv * Cv;
    const int r0 = blockIdx.y * 32, c0 = blockIdx.x * 32;
    #pragma unroll
    for (int k = 0; k < 4; k++) {
        int r = r0 + threadIdx.y + k * 8;
        t[threadIdx.y + k * 8][threadIdx.x] = in[zb + (size_t)r * Cv + c0 + threadIdx.x];
    }
    __syncthreads();
    #pragma unroll
    for (int k = 0; k < 4; k++) {
        int cc = c0 + threadIdx.y + k * 8;
        int rr = r0 + threadIdx.x;
        float v = t[threadIdx.x][threadIdx.y + k * 8];
        size_t o = zb + (size_t)cc * Cv + rr;
        bf16 h, l;
        bsplit(v, h, l);
        th[o] = h;
        tl[o] = l;
    }
}

// ---------------- box centers + zero LN stats ----------------
__global__ void pos_kernel(const float* __restrict__ box)
{
    int idx = blockIdx.x * blockDim.x + threadIdx.x;
    if (blockIdx.x == 0 && threadIdx.x < NGv * Bv * 2) g_stats[threadIdx.x] = 0.0;
    if (idx >= Bv * Sv) return;
    float cx = (box[idx * 4 + 0] + box[idx * 4 + 2]) * 0.5f;
    float cy = (box[idx * 4 + 1] + box[idx * 4 + 3]) * 0.5f;
    g_cx[idx] = cx; g_cy[idx] = cy; g_rr[idx] = cx * cx + cy * cy;
}

// ---------------- masked softmax -> bf16 hi/lo (+optional fp32 relation_graph) --------
__global__ __launch_bounds__(256)
void masked_softmax_kernel(const float* __restrict__ sim, bf16* __restrict__ aH,
                           bf16* __restrict__ aL, float* relF, const void* __restrict__ owp)
{
    const int row = blockIdx.x;
    const int b = row / Sv;
    const int tid = threadIdx.x;
    const float* srow = sim + (size_t)row * Sv;

    float ow = 224.0f;
    if (owp) {
        int vi = *(const int*)owp;
        ow = (vi > 0 && vi < 1000000) ? (float)vi : __int_as_float(vi);
    }
    const float thr2 = (0.2f * ow) * (0.2f * ow);

    const float rn = g_rr[row], cxn = g_cx[row], cyn = g_cy[row];
    const float* cxb = g_cx + b * Sv;
    const float* cyb = g_cy + b * Sv;
    const float* rb  = g_rr + b * Sv;

    float v[5];
    float mx = -INFINITY;
    #pragma unroll
    for (int u = 0; u < 5; u++) {
        int m = tid + u * 256;
        float d2 = (rn - 2.0f * (cxn * cxb[m] + cyn * cyb[m])) + rb[m];
        v[u] = (d2 > thr2) ? -INFINITY : srow[m];
        mx = fmaxf(mx, v[u]);
    }

    __shared__ float sh[8];
    #pragma unroll
    for (int o = 16; o > 0; o >>= 1) mx = fmaxf(mx, __shfl_xor_sync(0xffffffffu, mx, o));
    if ((tid & 31) == 0) sh[tid >> 5] = mx;
    __syncthreads();
    if (tid < 32) {
        float t = (tid < 8) ? sh[tid] : -INFINITY;
        #pragma unroll
        for (int o = 4; o > 0; o >>= 1) t = fmaxf(t, __shfl_xor_sync(0xffffffffu, t, o));
        if (tid == 0) sh[0] = t;
    }
    __syncthreads();
    mx = sh[0];
    __syncthreads();

    float sum = 0.f;
    #pragma unroll
    for (int u = 0; u < 5; u++) { v[u] = __expf(v[u] - mx); sum += v[u]; }
    #pragma unroll
    for (int o = 16; o > 0; o >>= 1) sum += __shfl_xor_sync(0xffffffffu, sum, o);
    if ((tid & 31) == 0) sh[tid >> 5] = sum;
    __syncthreads();
    if (tid < 32) {
        float t = (tid < 8) ? sh[tid] : 0.f;
        #pragma unroll
        for (int o = 4; o > 0; o >>= 1) t += __shfl_xor_sync(0xffffffffu, t, o);
        if (tid == 0) sh[0] = t;
    }
    __syncthreads();
    const float inv = 1.0f / sh[0];
    #pragma unroll
    for (int u = 0; u < 5; u++) {
        size_t o = (size_t)row * Sv + tid + u * 256;
        float p = v[u] * inv;
        bf16 h, l;
        bsplit(p, h, l);
        aH[o] = h;
        aL[o] = l;
        if (relF) relF[o] = p;
    }
}

// -------- finalize: out (+)= relu(LN(agg)*scale + bias), mu/rstd inline from stats ----
__global__ __launch_bounds__(256)
void finalize_kernel(const float* __restrict__ agg, const float* __restrict__ lns,
                     const float* __restrict__ lnb, float* __restrict__ out,
                     int first, const double* __restrict__ st)
{
    const size_t SC = (size_t)Sv * Cv;
    size_t idx = (size_t)blockIdx.x * blockDim.x + threadIdx.x;
    if (idx >= (size_t)Bv * SC) return;
    int b = (int)(idx / SC);
    int j = (int)(idx % SC);
    __shared__ float smu, srstd;
    if (threadIdx.x == 0) {
        const double n = (double)Sv * (double)Cv;
        double mu = st[b * 2 + 0] / n;
        double var = st[b * 2 + 1] / n - mu * mu;
        smu = (float)mu;
        srstd = rsqrtf((float)var + 1e-5f);
    }
    __syncthreads();
    float v = (agg[idx] - smu) * srstd * lns[j] + lnb[j];
    v = fmaxf(v, 0.f);
    out[idx] = first ? v : out[idx] + v;
}

// ---------------- launch ----------------
extern "C" void kernel_launch(void* const* d_in, const int* in_sizes, int n_in,
                              void* d_out, int out_size)
{
    const float* x   = (const float*)d_in[0];
    const float* box = (const float*)d_in[1];
    const float* Wt  = (const float*)d_in[2];
    const float* bt  = (const float*)d_in[3];
    const float* Wp  = (const float*)d_in[4];
    const float* bp  = (const float*)d_in[5];
    const float* Wg  = (const float*)d_in[6];
    const float* lns = (const float*)d_in[7];
    const float* lnb = (const float*)d_in[8];
    const void*  owp = (n_in > 10) ? d_in[10] : nullptr;

    float* out = (float*)d_out;
    float* rel = out + (size_t)Bv * Sv * Cv;

    bf16 *xh, *xl, *xth, *xtl, *wth, *wtl, *wph, *wpl, *wgh, *wgl;
    bf16 *thh, *thl, *phh, *phl, *ath, *atl, *tph, *tpl;
    float *sim, *agg;
    double *stats;
    cudaGetSymbolAddress((void**)&xh,  g_xh);  cudaGetSymbolAddress((void**)&xl,  g_xl);
    cudaGetSymbolAddress((void**)&xth, g_xth); cudaGetSymbolAddress((void**)&xtl, g_xtl);
    cudaGetSymbolAddress((void**)&wth, g_wth); cudaGetSymbolAddress((void**)&wtl, g_wtl);
    cudaGetSymbolAddress((void**)&wph, g_wph); cudaGetSymbolAddress((void**)&wpl, g_wpl);
    cudaGetSymbolAddress((void**)&wgh, g_wgh); cudaGetSymbolAddress((void**)&wgl, g_wgl);
    cudaGetSymbolAddress((void**)&thh, g_thh); cudaGetSymbolAddress((void**)&thl, g_thl);
    cudaGetSymbolAddress((void**)&phh, g_phh); cudaGetSymbolAddress((void**)&phl, g_phl);
    cudaGetSymbolAddress((void**)&sim, g_sim);
    cudaGetSymbolAddress((void**)&ath, g_ath); cudaGetSymbolAddress((void**)&atl, g_atl);
    cudaGetSymbolAddress((void**)&tph, g_tph); cudaGetSymbolAddress((void**)&tpl, g_tpl);
    cudaGetSymbolAddress((void**)&agg, g_agg);
    cudaGetSymbolAddress((void**)&stats, g_stats);

    cudaFuncSetAttribute(tcgemm, cudaFuncAttributeMaxDynamicSharedMemorySize, DYN_BYTES);

    const size_t sSC = (size_t)Sv * Cv;
    const size_t sSS = (size_t)Sv * Sv;
    const size_t sCC = (size_t)Cv * Cv;
    const size_t sCS = (size_t)Cv * Sv;
    const float inv_sqrt = 0.04419417382415922f;
    const int NOSPLIT = 1 << 30;

    // stream B: theta/phi prefetch only. stream C: agg+finalize epilogue only.
    // (R15 lesson: sharing one side stream serializes prefetch behind epilogue.)
    cudaStream_t sB, sC;
    cudaStreamCreateWithFlags(&sB, cudaStreamNonBlocking);
    cudaStreamCreateWithFlags(&sC, cudaStreamNonBlocking);
    cudaEvent_t evFork, evT[NGv], evS[NGv], evM[NGv], evA[NGv];
    cudaEventCreateWithFlags(&evFork, cudaEventDisableTiming);
    for (int i = 0; i < NGv; i++) {
        cudaEventCreateWithFlags(&evT[i], cudaEventDisableTiming);
        cudaEventCreateWithFlags(&evS[i], cudaEventDisableTiming);
        cudaEventCreateWithFlags(&evM[i], cudaEventDisableTiming);
        cudaEventCreateWithFlags(&evA[i], cudaEventDisableTiming);
    }

    pos_kernel<<<(Bv * Sv + 255) / 256, 256>>>(box);
    conv_x_kernel<<<dim3(Cv / 32, Sv / 32, Bv), dim3(32, 8)>>>(x, xth, xtl, xh, xl);
    conv_w_kernel<<<dim3(Cv / 32, Cv / 32, 3 * NGv), dim3(32, 8)>>>(
        Wt, Wp, Wg, wth, wtl, wph, wpl, wgh, wgl);

    cudaEventRecord(evFork, 0);
    cudaStreamWaitEvent(sB, evFork, 0);
    cudaStreamWaitEvent(sC, evFork, 0);

    for (int i = 0; i < NGv; i++) {
        const int set = i & 1;
        bf16* thhS = thh + (size_t)set * Bv * sSC;
        bf16* thlS = thl + (size_t)set * Bv * sSC;
        bf16* phhS = phh + (size_t)set * Bv * sSC;
        bf16* phlS = phl + (size_t)set * Bv * sSC;
        bf16* tphS = tph + (size_t)set * Bv * sSC;
        bf16* tplS = tpl + (size_t)set * Bv * sSC;

        // ---- stream B: theta & phi for subgraph i (waits sim(i-2) = last reader of set)
        if (i >= 2) cudaStreamWaitEvent(sB, evS[i - 2], 0);
        tcgemm<<<dim3(2, 10, 16), 160, DYN_BYTES, sB>>>(
            xh, xl, sSC, Cv,
            wth + i * sCC, wtl + i * sCC, wph + i * sCC, wpl + i * sCC, 0, Cv,
            nullptr, thhS, thlS, phhS, phlS, sSC, Cv,
            bt + (size_t)i * Cv, bp + (size_t)i * Cv, 1.0f, Cv, 8, nullptr);
        cudaEventRecord(evT[i], sB);

        // ---- main stream: sim -> softmax -> tmp ----
        cudaStreamWaitEvent(0, evT[i], 0);
        tcgemm<<<dim3(5, 10, 8), 160, DYN_BYTES>>>(
            thhS, thlS, sSC, Cv,
            phhS, phlS, nullptr, nullptr, sSC, Cv,
            sim, nullptr, nullptr, nullptr, nullptr, sSS, Sv,
            nullptr, nullptr, inv_sqrt, Cv, NOSPLIT, nullptr);
        cudaEventRecord(evS[i], 0);

        masked_softmax_kernel<<<Bv * Sv, 256>>>(sim, ath, atl, (i == NGv - 1) ? rel : nullptr, owp);

        // tmp(i) writes tph[set]; agg(i-2) on stream C was the last reader of that set
        if (i >= 2) cudaStreamWaitEvent(0, evA[i - 2], 0);
        tcgemm<<<dim3(2, 10, 8), 160, DYN_BYTES>>>(
            ath, atl, sSS, Sv,
            xth, xtl, nullptr, nullptr, sCS, Sv,
            nullptr, tphS, tplS, nullptr, nullptr, sSC, Cv,
            nullptr, nullptr, 1.0f, Sv, NOSPLIT, nullptr);
        cudaEventRecord(evM[i], 0);

        // ---- stream C: agg + finalize (off critical path; serial in i on C) ----
        cudaStreamWaitEvent(sC, evM[i], 0);
        tcgemm<<<dim3(2, 10, 8), 160, DYN_BYTES, sC>>>(
            tphS, tplS, sSC, Cv,
            wgh + i * sCC, wgl + i * sCC, nullptr, nullptr, 0, Cv,
            agg, nullptr, nullptr, nullptr, nullptr, sSC, Cv,
            nullptr, nullptr, 1.0f, Cv, NOSPLIT, stats + (size_t)i * Bv * 2);

        finalize_kernel<<<(int)((sSC * Bv + 255) / 256), 256, 0, sC>>>(
            agg, lns + (size_t)i * sSC, lnb + (size_t)i * sSC, out,
            i == 0 ? 1 : 0, stats + (size_t)i * Bv * 2);
        cudaEventRecord(evA[i], sC);
    }

    // join stream C back to the origin stream (last writes to `out` happen on C)
    cudaStreamWaitEvent(0, evA[NGv - 1], 0);

    cudaEventDestroy(evFork);
    for (int i = 0; i < NGv; i++) {
        cudaEventDestroy(evT[i]); cudaEventDestroy(evS[i]);
        cudaEventDestroy(evM[i]); cudaEventDestroy(evA[i]);
    }
    cudaStreamDestroy(sB);
    cudaStreamDestroy(sC);
}

// round 17
// speedup vs baseline: 1.3028x; 1.0643x over previous
#include <cuda_runtime.h>
#include <cuda_bf16.h>
#include <math.h>
#include <stdint.h>

#define NGv 12
#define Bv  8
#define Sv  1280
#define Cv  512
#define BSv (Bv * Sv)

typedef __nv_bfloat16 bf16;

// ---------------- device scratch ----------------
__device__ bf16  g_xh [Bv*Sv*Cv], g_xl [Bv*Sv*Cv];
__device__ bf16  g_xth[Bv*Cv*Sv], g_xtl[Bv*Cv*Sv];
__device__ bf16  g_wth[NGv*Cv*Cv], g_wtl[NGv*Cv*Cv];
__device__ bf16  g_wph[NGv*Cv*Cv], g_wpl[NGv*Cv*Cv];
__device__ bf16  g_wgh[NGv*Cv*Cv], g_wgl[NGv*Cv*Cv];
__device__ bf16  g_thh[2*Bv*Sv*Cv], g_thl[2*Bv*Sv*Cv];   // theta double-buffered (set = i&1)
__device__ bf16  g_phh[2*Bv*Sv*Cv], g_phl[2*Bv*Sv*Cv];   // phi double-buffered
__device__ float g_sim[Bv*Sv*Sv];
__device__ bf16  g_ath[2*Bv*Sv*Sv], g_atl[2*Bv*Sv*Sv];   // attn double-buffered (set = i&1)
__device__ bf16  g_tph[2*Bv*Sv*Cv], g_tpl[2*Bv*Sv*Cv];   // tmp double-buffered (set = i&1)
__device__ float g_agg[Bv*Sv*Cv];
__device__ float g_cx[Bv*Sv], g_cy[Bv*Sv], g_rr[Bv*Sv];
__device__ double g_stats[NGv*Bv*2];

// ---------------- helpers ----------------
__device__ __forceinline__ uint32_t sm2u(const void* p) {
    uint32_t a;
    asm("{ .reg .u64 t; cvta.to.shared.u64 t, %1; cvt.u32.u64 %0, t; }" : "=r"(a) : "l"(p));
    return a;
}
// SW64 swizzle: 64B rows, atom = 8 rows x 64B (proven in R11)
#define SWZ64(o) ((o) ^ (((o) >> 3) & 0x30u))

__device__ __forceinline__ void bsplit(float x, bf16& h, bf16& l) {
    h = __float2bfloat16(x);
    l = __float2bfloat16(x - __bfloat162float(h));
}

__device__ __forceinline__ void cpasync16(uint32_t dst, const void* src) {
    asm volatile("cp.async.cg.shared.global [%0], [%1], 16;" :: "r"(dst), "l"(src));
}
// .noinc is load-bearing (R4 deadlock otherwise).
__device__ __forceinline__ void cpasync_arrive_noinc(uint32_t bar) {
    asm volatile("cp.async.mbarrier.arrive.noinc.shared.b64 [%0];" :: "r"(bar));
}
__device__ __forceinline__ void mbar_init(uint32_t bar, uint32_t cnt) {
    asm volatile("mbarrier.init.shared.b64 [%0], %1;" :: "r"(bar), "r"(cnt) : "memory");
}
__device__ __forceinline__ void mbar_wait(uint32_t bar, uint32_t parity) {
    asm volatile(
        "{\n\t"
        ".reg .pred P;\n\t"
        "WL%=:\n\t"
        "mbarrier.try_wait.parity.acquire.cta.shared::cta.b64 P, [%0], %1;\n\t"
        "@P bra WD%=;\n\t"
        "bra WL%=;\n\t"
        "WD%=:\n\t"
        "}"
        :: "r"(bar), "r"(parity) : "memory");
}
__device__ __forceinline__ void fence_proxy_async_cta() {
    asm volatile("fence.proxy.async.shared::cta;" ::: "memory");
}
__device__ __forceinline__ void kahan(float& s, float& c, float v) {
    float y = v - c;
    float t = s + y;
    c = (t - s) - y;
    s = t;
}

#if defined(__CUDA_ARCH_FEAT_SM103_ALL) || !defined(__CUDA_ARCH__)
#define HAS_TCGEN05 1
#else
#define HAS_TCGEN05 0
#endif

#if HAS_TCGEN05
__device__ __forceinline__ void tc_commit(uint32_t bar) {
    asm volatile("tcgen05.commit.cta_group::1.mbarrier::arrive::one.shared::cluster.b64 [%0];"
                 :: "r"(bar) : "memory");
}
__device__ __forceinline__ void mma_bf16(uint32_t d, uint64_t ad, uint64_t bd, uint32_t idesc, bool acc) {
    uint32_t e = acc ? 1u : 0u;
    asm volatile(
        "{\n\t"
        ".reg .pred p;\n\t"
        "setp.ne.u32 p, %4, 0;\n\t"
        "tcgen05.mma.cta_group::1.kind::f16 [%0], %1, %2, %3, p;\n\t"
        "}"
        :: "r"(d), "l"(ad), "l"(bd), "r"(idesc), "r"(e) : "memory");
}
#define TC_ALLOC(smemaddr, n) \
    asm volatile("tcgen05.alloc.cta_group::1.sync.aligned.shared::cta.b32 [%0], %1;" \
                 :: "r"(smemaddr), "r"((uint32_t)(n)) : "memory")
#define TC_RELINQ() \
    asm volatile("tcgen05.relinquish_alloc_permit.cta_group::1.sync.aligned;")
#define TC_DEALLOC(tm, n) \
    asm volatile("tcgen05.dealloc.cta_group::1.sync.aligned.b32 %0, %1;" :: "r"(tm), "r"((uint32_t)(n)))
#define TC_FENCE_AFTER()  asm volatile("tcgen05.fence::after_thread_sync;" ::: "memory")
#define TC_WAIT_LD()      asm volatile("tcgen05.wait::ld.sync.aligned;" ::: "memory")
#define LDTM32(r, a) \
    asm volatile( \
        "tcgen05.ld.sync.aligned.32x32b.x32.b32 " \
        "{%0, %1, %2, %3, %4, %5, %6, %7, " \
        " %8, %9, %10, %11, %12, %13, %14, %15, " \
        " %16, %17, %18, %19, %20, %21, %22, %23, " \
        " %24, %25, %26, %27, %28, %29, %30, %31}, [%32];" \
        : "=r"((r)[0]),  "=r"((r)[1]),  "=r"((r)[2]),  "=r"((r)[3]), \
          "=r"((r)[4]),  "=r"((r)[5]),  "=r"((r)[6]),  "=r"((r)[7]), \
          "=r"((r)[8]),  "=r"((r)[9]),  "=r"((r)[10]), "=r"((r)[11]), \
          "=r"((r)[12]), "=r"((r)[13]), "=r"((r)[14]), "=r"((r)[15]), \
          "=r"((r)[16]), "=r"((r)[17]), "=r"((r)[18]), "=r"((r)[19]), \
          "=r"((r)[20]), "=r"((r)[21]), "=r"((r)[22]), "=r"((r)[23]), \
          "=r"((r)[24]), "=r"((r)[25]), "=r"((r)[26]), "=r"((r)[27]), \
          "=r"((r)[28]), "=r"((r)[29]), "=r"((r)[30]), "=r"((r)[31]) \
        : "r"(a))
#endif

// SW64 descriptor: layout=4, version=1 (Blackwell), SBO=32 (8 rows x 64B /16), LBO=1
static constexpr uint64_t DESC_BASE_SW64 =
    (4ull << 61) | (1ull << 46) | (32ull << 32) | (1ull << 16);
__device__ __forceinline__ uint64_t mk_desc(uint32_t addr) {
    return DESC_BASE_SW64 | ((uint64_t)(addr >> 4) & 0x3FFFull);
}

// idesc (kind::f16): dtype=F32, atype=BF16, btype=BF16, N=256, M=128
static constexpr uint32_t IDESC_BF = (1u << 4) | (1u << 7) | (1u << 10) | (32u << 17) | (8u << 24);

// ---------------- tcgen05 3xBF16 GEMM (R11-proven): D = alpha*(A @ B^T) + bias -------
// KC=32 (64B rows, SW64), stage 48KB, 2 stages = 96KB -> 2 CTAs/SM.
#define KC 32
#define OFF_AL 8192
#define OFF_BH 16384
#define OFF_BL 32768
#define STG_BYTES 49152
#define DYN_BYTES 98304

__global__ __launch_bounds__(160, 2)
void tcgemm(const bf16* __restrict__ Ah, const bf16* __restrict__ Al, size_t sAz, int ldA,
            const bf16* __restrict__ Bh, const bf16* __restrict__ Bl,
            const bf16* __restrict__ Bh2, const bf16* __restrict__ Bl2, size_t sBz, int ldB,
            float* outF, bf16* outH, bf16* outL, bf16* outH2, bf16* outL2,
            size_t sOz, int ldO,
            const float* bias, const float* bias2, float alpha, int K, int zsplit,
            double* statsBase)
{
    int z = blockIdx.z;
    if (z >= zsplit) { z -= zsplit; Bh = Bh2; Bl = Bl2; outH = outH2; outL = outL2; bias = bias2; }
    const int m0   = blockIdx.y * 128;
    const int col0 = blockIdx.x * 256;

#if HAS_TCGEN05
    extern __shared__ __align__(1024) char dynsm[];
    __shared__ __align__(8) uint64_t s_full[2], s_empty[2], s_done;
    __shared__ uint32_t s_tptr;
    __shared__ float s_red[8];

    const int tid = threadIdx.x;
    const int wid = tid >> 5;
    const int lane = tid & 31;

    const uint32_t dynu = sm2u(dynsm);
    uint32_t fullb[2]  = { sm2u(&s_full[0]),  sm2u(&s_full[1])  };
    uint32_t emptyb[2] = { sm2u(&s_empty[0]), sm2u(&s_empty[1]) };
    const uint32_t doneb = sm2u(&s_done);

    if (tid == 0) {
        mbar_init(fullb[0], 128); mbar_init(fullb[1], 128);
        mbar_init(emptyb[0], 1);  mbar_init(emptyb[1], 1);
        mbar_init(doneb, 1);
    }
    __syncthreads();
    if (wid == 4) {
        TC_ALLOC(sm2u(&s_tptr), 256);
        TC_RELINQ();
    }
    __syncthreads();
    const uint32_t tmem = s_tptr;

    const int nk = K / KC;

    if (wid < 4) {
        // ---- producers (128 threads); rows are 64B (KC=32 bf16) ----
        const bf16* aH = Ah + (size_t)z * sAz + (size_t)m0 * ldA;
        const bf16* aL = Al + (size_t)z * sAz + (size_t)m0 * ldA;
        const bf16* bH = Bh + (size_t)z * sBz + (size_t)col0 * ldB;
        const bf16* bL = Bl + (size_t)z * sBz + (size_t)col0 * ldB;
        int st = 0, ph = 1;
        for (int c = 0; c < nk; c++) {
            mbar_wait(emptyb[st], ph);
            const uint32_t sb = dynu + st * STG_BYTES;
            const int k0 = c * KC;
            #pragma unroll
            for (int i = 0; i < 4; i++) {
                int idx = i * 128 + tid;
                int r = idx >> 2, cc = idx & 3;
                uint32_t so = SWZ64((uint32_t)(r * 64 + cc * 16));
                const size_t go = (size_t)r * ldA + k0 + cc * 8;
                cpasync16(sb + so, aH + go);
                cpasync16(sb + OFF_AL + so, aL + go);
            }
            #pragma unroll
            for (int i = 0; i < 8; i++) {
                int idx = i * 128 + tid;
                int r = idx >> 2, cc = idx & 3;
                uint32_t so = SWZ64((uint32_t)(r * 64 + cc * 16));
                const size_t go = (size_t)r * ldB + k0 + cc * 8;
                cpasync16(sb + OFF_BH + so, bH + go);
                cpasync16(sb + OFF_BL + so, bL + go);
            }
            cpasync_arrive_noinc(fullb[st]);
            if (++st == 2) { st = 0; ph ^= 1; }
        }
    } else if (lane == 0) {
        // ---- MMA issuer: 2 K-steps (16 bf16 each) x {hh, hl, lh} per chunk ----
        int st = 0, ph = 0;
        for (int c = 0; c < nk; c++) {
            mbar_wait(fullb[st], ph);
            fence_proxy_async_cta();
            const uint32_t sb = dynu + st * STG_BYTES;
            uint64_t dah = mk_desc(sb),          dal = mk_desc(sb + OFF_AL);
            uint64_t dbh = mk_desc(sb + OFF_BH), dbl = mk_desc(sb + OFF_BL);
            #pragma unroll
            for (int ks = 0; ks < 2; ks++)
                mma_bf16(tmem, dah + ks * 2, dbh + ks * 2, IDESC_BF, !(c == 0 && ks == 0));
            #pragma unroll
            for (int ks = 0; ks < 2; ks++)
                mma_bf16(tmem, dah + ks * 2, dbl + ks * 2, IDESC_BF, true);
            #pragma unroll
            for (int ks = 0; ks < 2; ks++)
                mma_bf16(tmem, dal + ks * 2, dbh + ks * 2, IDESC_BF, true);
            tc_commit(emptyb[st]);
            if (++st == 2) { st = 0; ph ^= 1; }
        }
        tc_commit(doneb);
    }

    mbar_wait(doneb, 0);
    TC_FENCE_AFTER();

    const bool dostats = (statsBase != nullptr);
    float sacc = 0.f, sc = 0.f, qacc = 0.f, qc = 0.f;

    if (wid < 4) {
        float* tile = (float*)(dynsm + wid * 4352);     // 32x33 floats per warp
        const size_t obase = (size_t)z * sOz;
        for (int c0 = 0; c0 < 256; c0 += 32) {
            uint32_t regs[32];
            LDTM32(regs, tmem + c0);
            TC_WAIT_LD();
            #pragma unroll
            for (int j = 0; j < 32; j++) {
                float v = __uint_as_float(regs[j]) * alpha;
                if (bias) v += bias[col0 + c0 + j];
                tile[lane * 33 + j] = v;
                if (dostats) { kahan(sacc, sc, v); kahan(qacc, qc, v * v); }
            }
            __syncwarp();
            #pragma unroll
            for (int i = 0; i < 8; i++) {
                int f = i * 32 + lane;
                int rr = f >> 3, q = (f & 7) * 4;
                float vv[4];
                vv[0] = tile[rr * 33 + q + 0];
                vv[1] = tile[rr * 33 + q + 1];
                vv[2] = tile[rr * 33 + q + 2];
                vv[3] = tile[rr * 33 + q + 3];
                size_t off = obase + (size_t)(m0 + wid * 32 + rr) * ldO + col0 + c0 + q;
                if (outF) {
                    float4 o4 = { vv[0], vv[1], vv[2], vv[3] };
                    *(float4*)(outF + off) = o4;
                }
                if (outH) {
                    uint32_t hw[4], lw[4];
                    #pragma unroll
                    for (int t = 0; t < 4; t++) {
                        bf16 h, l;
                        bsplit(vv[t], h, l);
                        hw[t] = (uint32_t)__bfloat16_as_ushort(h);
                        lw[t] = (uint32_t)__bfloat16_as_ushort(l);
                    }
                    uint2 uh = { hw[0] | (hw[1] << 16), hw[2] | (hw[3] << 16) };
                    uint2 ul = { lw[0] | (lw[1] << 16), lw[2] | (lw[3] << 16) };
                    *(uint2*)(outH + off) = uh;
                    *(uint2*)(outL + off) = ul;
                }
            }
            __syncwarp();
        }
        if (dostats) {
            #pragma unroll
            for (int o = 16; o > 0; o >>= 1) {
                sacc += __shfl_xor_sync(0xffffffffu, sacc, o);
                qacc += __shfl_xor_sync(0xffffffffu, qacc, o);
            }
            if (lane == 0) { s_red[wid] = sacc; s_red[4 + wid] = qacc; }
        }
    }
    __syncthreads();
    if (dostats && tid == 0) {
        double s = (double)s_red[0] + s_red[1] + s_red[2] + s_red[3];
        double q = (double)s_red[4] + s_red[5] + s_red[6] + s_red[7];
        atomicAdd(&statsBase[z * 2 + 0], s);
        atomicAdd(&statsBase[z * 2 + 1], q);
    }
    if (wid == 4) TC_DEALLOC(tmem, 256);
#else
    // -------- plain-sm_103 fallback (insurance; never the selected cubin) --------
    const bf16* aH = Ah + (size_t)z * sAz;
    const bf16* aL = Al + (size_t)z * sAz;
    const bf16* bH = Bh + (size_t)z * sBz;
    const bf16* bL = Bl + (size_t)z * sBz;
    for (int idx = threadIdx.x; idx < 128 * 256; idx += blockDim.x) {
        int mi = m0 + (idx >> 8);
        int ni = col0 + (idx & 255);
        const bf16* pa  = aH + (size_t)mi * ldA;
        const bf16* pa2 = aL + (size_t)mi * ldA;
        const bf16* pb  = bH + (size_t)ni * ldB;
        const bf16* pb2 = bL + (size_t)ni * ldB;
        float s = 0.f;
        for (int k = 0; k < K; k++)
            s += (__bfloat162float(pa[k]) + __bfloat162float(pa2[k])) *
                 (__bfloat162float(pb[k]) + __bfloat162float(pb2[k]));
        float v = s * alpha + (bias ? bias[ni] : 0.f);
        size_t off = (size_t)z * sOz + (size_t)mi * ldO + ni;
        if (outF) outF[off] = v;
        if (outH) {
            bf16 h, l;
            bsplit(v, h, l);
            outH[off] = h;
            outL[off] = l;
        }
        if (statsBase) {
            atomicAdd(&statsBase[z * 2 + 0], (double)v);
            atomicAdd(&statsBase[z * 2 + 1], (double)v * (double)v);
        }
    }
#endif
}

// ---------------- x: straight split + transposed split ----------
__global__ void conv_x_kernel(const float* __restrict__ in, bf16* __restrict__ th,
                              bf16* __restrict__ tl, bf16* __restrict__ sh,
                              bf16* __restrict__ sl)
{
    __shared__ float t[32][33];
    const int z = blockIdx.z;
    const size_t zb = (size_t)z * Sv * Cv;
    const int r0 = blockIdx.y * 32, c0 = blockIdx.x * 32;
    #pragma unroll
    for (int k = 0; k < 4; k++) {
        int r = r0 + threadIdx.y + k * 8;
        size_t idx = zb + (size_t)r * Cv + c0 + threadIdx.x;
        float v = in[idx];
        t[threadIdx.y + k * 8][threadIdx.x] = v;
        bf16 h, l;
        bsplit(v, h, l);
        sh[idx] = h;
        sl[idx] = l;
    }
    __syncthreads();
    #pragma unroll
    for (int k = 0; k < 4; k++) {
        int cc = c0 + threadIdx.y + k * 8;
        int rr = r0 + threadIdx.x;
        float v = t[threadIdx.x][threadIdx.y + k * 8];
        size_t o = zb + (size_t)cc * Sv + rr;
        bf16 h, l;
        bsplit(v, h, l);
        th[o] = h;
        tl[o] = l;
    }
}

// ---------------- all weights: transposed split in ONE launch (z = 3*NG) -------------
__global__ void conv_w_kernel(const float* __restrict__ Wt, const float* __restrict__ Wp,
                              const float* __restrict__ Wg,
                              bf16* __restrict__ wth, bf16* __restrict__ wtl,
                              bf16* __restrict__ wph, bf16* __restrict__ wpl,
                              bf16* __restrict__ wgh, bf16* __restrict__ wgl)
{
    __shared__ float t[32][33];
    const int z = blockIdx.z;
    const int w = z / NGv, i = z % NGv;
    const float* in = (w == 0 ? Wt : (w == 1 ? Wp : Wg));
    bf16* th = (w == 0 ? wth : (w == 1 ? wph : wgh));
    bf16* tl = (w == 0 ? wtl : (w == 1 ? wpl : wgl));
    const size_t zb = (size_t)i * Cv * Cv;
    const int r0 = blockIdx.y * 32, c0 = blockIdx.x * 32;
    #pragma unroll
    for (int k = 0; k < 4; k++) {
        int r = r0 + threadIdx.y + k * 8;
        t[threadIdx.y + k * 8][threadIdx.x] = in[zb + (size_t)r * Cv + c0 + threadIdx.x];
    }
    __syncthreads();
    #pragma unroll
    for (int k = 0; k < 4; k++) {
        int cc = c0 + threadIdx.y + k * 8;
        int rr = r0 + threadIdx.x;
        float v = t[threadIdx.x][threadIdx.y + k * 8];
        size_t o = zb + (size_t)cc * Cv + rr;
        bf16 h, l;
        bsplit(v, h, l);
        th[o] = h;
        tl[o] = l;
    }
}

// ---------------- box centers + zero LN stats ----------------
__global__ void pos_kernel(const float* __restrict__ box)
{
    int idx = blockIdx.x * blockDim.x + threadIdx.x;
    if (blockIdx.x == 0 && threadIdx.x < NGv * Bv * 2) g_stats[threadIdx.x] = 0.0;
    if (idx >= Bv * Sv) return;
    float cx = (box[idx * 4 + 0] + box[idx * 4 + 2]) * 0.5f;
    float cy = (box[idx * 4 + 1] + box[idx * 4 + 3]) * 0.5f;
    g_cx[idx] = cx; g_cy[idx] = cy; g_rr[idx] = cx * cx + cy * cy;
}

// ---------------- masked softmax -> bf16 hi/lo (+optional fp32 relation_graph) --------
__global__ __launch_bounds__(256)
void masked_softmax_kernel(const float* __restrict__ sim, bf16* __restrict__ aH,
                           bf16* __restrict__ aL, float* relF, const void* __restrict__ owp)
{
    const int row = blockIdx.x;
    const int b = row / Sv;
    const int tid = threadIdx.x;
    const float* srow = sim + (size_t)row * Sv;

    float ow = 224.0f;
    if (owp) {
        int vi = *(const int*)owp;
        ow = (vi > 0 && vi < 1000000) ? (float)vi : __int_as_float(vi);
    }
    const float thr2 = (0.2f * ow) * (0.2f * ow);

    const float rn = g_rr[row], cxn = g_cx[row], cyn = g_cy[row];
    const float* cxb = g_cx + b * Sv;
    const float* cyb = g_cy + b * Sv;
    const float* rb  = g_rr + b * Sv;

    float v[5];
    float mx = -INFINITY;
    #pragma unroll
    for (int u = 0; u < 5; u++) {
        int m = tid + u * 256;
        float d2 = (rn - 2.0f * (cxn * cxb[m] + cyn * cyb[m])) + rb[m];
        v[u] = (d2 > thr2) ? -INFINITY : srow[m];
        mx = fmaxf(mx, v[u]);
    }

    __shared__ float sh[8];
    #pragma unroll
    for (int o = 16; o > 0; o >>= 1) mx = fmaxf(mx, __shfl_xor_sync(0xffffffffu, mx, o));
    if ((tid & 31) == 0) sh[tid >> 5] = mx;
    __syncthreads();
    if (tid < 32) {
        float t = (tid < 8) ? sh[tid] : -INFINITY;
        #pragma unroll
        for (int o = 4; o > 0; o >>= 1) t = fmaxf(t, __shfl_xor_sync(0xffffffffu, t, o));
        if (tid == 0) sh[0] = t;
    }
    __syncthreads();
    mx = sh[0];
    __syncthreads();

    float sum = 0.f;
    #pragma unroll
    for (int u = 0; u < 5; u++) { v[u] = __expf(v[u] - mx); sum += v[u]; }
    #pragma unroll
    for (int o = 16; o > 0; o >>= 1) sum += __shfl_xor_sync(0xffffffffu, sum, o);
    if ((tid & 31) == 0) sh[tid >> 5] = sum;
    __syncthreads();
    if (tid < 32) {
        float t = (tid < 8) ? sh[tid] : 0.f;
        #pragma unroll
        for (int o = 4; o > 0; o >>= 1) t += __shfl_xor_sync(0xffffffffu, t, o);
        if (tid == 0) sh[0] = t;
    }
    __syncthreads();
    const float inv = 1.0f / sh[0];
    #pragma unroll
    for (int u = 0; u < 5; u++) {
        size_t o = (size_t)row * Sv + tid + u * 256;
        float p = v[u] * inv;
        bf16 h, l;
        bsplit(p, h, l);
        aH[o] = h;
        aL[o] = l;
        if (relF) relF[o] = p;
    }
}

// -------- finalize: out (+)= relu(LN(agg)*scale + bias), mu/rstd inline from stats ----
__global__ __launch_bounds__(256)
void finalize_kernel(const float* __restrict__ agg, const float* __restrict__ lns,
                     const float* __restrict__ lnb, float* __restrict__ out,
                     int first, const double* __restrict__ st)
{
    const size_t SC = (size_t)Sv * Cv;
    size_t idx = (size_t)blockIdx.x * blockDim.x + threadIdx.x;
    if (idx >= (size_t)Bv * SC) return;
    int b = (int)(idx / SC);
    int j = (int)(idx % SC);
    __shared__ float smu, srstd;
    if (threadIdx.x == 0) {
        const double n = (double)Sv * (double)Cv;
        double mu = st[b * 2 + 0] / n;
        double var = st[b * 2 + 1] / n - mu * mu;
        smu = (float)mu;
        srstd = rsqrtf((float)var + 1e-5f);
    }
    __syncthreads();
    float v = (agg[idx] - smu) * srstd * lns[j] + lnb[j];
    v = fmaxf(v, 0.f);
    out[idx] = first ? v : out[idx] + v;
}

// ---------------- launch ----------------
extern "C" void kernel_launch(void* const* d_in, const int* in_sizes, int n_in,
                              void* d_out, int out_size)
{
    const float* x   = (const float*)d_in[0];
    const float* box = (const float*)d_in[1];
    const float* Wt  = (const float*)d_in[2];
    const float* bt  = (const float*)d_in[3];
    const float* Wp  = (const float*)d_in[4];
    const float* bp  = (const float*)d_in[5];
    const float* Wg  = (const float*)d_in[6];
    const float* lns = (const float*)d_in[7];
    const float* lnb = (const float*)d_in[8];
    const void*  owp = (n_in > 10) ? d_in[10] : nullptr;

    float* out = (float*)d_out;
    float* rel = out + (size_t)Bv * Sv * Cv;

    bf16 *xh, *xl, *xth, *xtl, *wth, *wtl, *wph, *wpl, *wgh, *wgl;
    bf16 *thh, *thl, *phh, *phl, *ath, *atl, *tph, *tpl;
    float *sim, *agg;
    double *stats;
    cudaGetSymbolAddress((void**)&xh,  g_xh);  cudaGetSymbolAddress((void**)&xl,  g_xl);
    cudaGetSymbolAddress((void**)&xth, g_xth); cudaGetSymbolAddress((void**)&xtl, g_xtl);
    cudaGetSymbolAddress((void**)&wth, g_wth); cudaGetSymbolAddress((void**)&wtl, g_wtl);
    cudaGetSymbolAddress((void**)&wph, g_wph); cudaGetSymbolAddress((void**)&wpl, g_wpl);
    cudaGetSymbolAddress((void**)&wgh, g_wgh); cudaGetSymbolAddress((void**)&wgl, g_wgl);
    cudaGetSymbolAddress((void**)&thh, g_thh); cudaGetSymbolAddress((void**)&thl, g_thl);
    cudaGetSymbolAddress((void**)&phh, g_phh); cudaGetSymbolAddress((void**)&phl, g_phl);
    cudaGetSymbolAddress((void**)&sim, g_sim);
    cudaGetSymbolAddress((void**)&ath, g_ath); cudaGetSymbolAddress((void**)&atl, g_atl);
    cudaGetSymbolAddress((void**)&tph, g_tph); cudaGetSymbolAddress((void**)&tpl, g_tpl);
    cudaGetSymbolAddress((void**)&agg, g_agg);
    cudaGetSymbolAddress((void**)&stats, g_stats);

    cudaFuncSetAttribute(tcgemm, cudaFuncAttributeMaxDynamicSharedMemorySize, DYN_BYTES);

    const size_t sSC = (size_t)Sv * Cv;
    const size_t sSS = (size_t)Sv * Sv;
    const size_t sCC = (size_t)Cv * Cv;
    const size_t sCS = (size_t)Cv * Sv;
    const float inv_sqrt = 0.04419417382415922f;
    const int NOSPLIT = 1 << 30;

    // sM (high prio): sim+softmax critical chain. sB (low): theta/phi prefetch.
    // sC (low): tmp->agg->finalize epilogue chain.
    int prLo = 0, prHi = 0;
    cudaDeviceGetStreamPriorityRange(&prLo, &prHi);
    cudaStream_t sM, sB, sC;
    cudaStreamCreateWithPriority(&sM, cudaStreamNonBlocking, prHi);
    cudaStreamCreateWithPriority(&sB, cudaStreamNonBlocking, prLo);
    cudaStreamCreateWithPriority(&sC, cudaStreamNonBlocking, prLo);
    cudaEvent_t evFork, evT[NGv], evS[NGv], evSM[NGv], evTm[NGv], evA[NGv];
    cudaEventCreateWithFlags(&evFork, cudaEventDisableTiming);
    for (int i = 0; i < NGv; i++) {
        cudaEventCreateWithFlags(&evT[i], cudaEventDisableTiming);
        cudaEventCreateWithFlags(&evS[i], cudaEventDisableTiming);
        cudaEventCreateWithFlags(&evSM[i], cudaEventDisableTiming);
        cudaEventCreateWithFlags(&evTm[i], cudaEventDisableTiming);
        cudaEventCreateWithFlags(&evA[i], cudaEventDisableTiming);
    }

    pos_kernel<<<(Bv * Sv + 255) / 256, 256>>>(box);
    conv_x_kernel<<<dim3(Cv / 32, Sv / 32, Bv), dim3(32, 8)>>>(x, xth, xtl, xh, xl);
    conv_w_kernel<<<dim3(Cv / 32, Cv / 32, 3 * NGv), dim3(32, 8)>>>(
        Wt, Wp, Wg, wth, wtl, wph, wpl, wgh, wgl);

    cudaEventRecord(evFork, 0);
    cudaStreamWaitEvent(sM, evFork, 0);
    cudaStreamWaitEvent(sB, evFork, 0);
    cudaStreamWaitEvent(sC, evFork, 0);

    for (int i = 0; i < NGv; i++) {
        const int set = i & 1;
        bf16* thhS = thh + (size_t)set * Bv * sSC;
        bf16* thlS = thl + (size_t)set * Bv * sSC;
        bf16* phhS = phh + (size_t)set * Bv * sSC;
        bf16* phlS = phl + (size_t)set * Bv * sSC;
        bf16* athS = ath + (size_t)set * Bv * sSS;
        bf16* atlS = atl + (size_t)set * Bv * sSS;
        bf16* tphS = tph + (size_t)set * Bv * sSC;
        bf16* tplS = tpl + (size_t)set * Bv * sSC;

        // ---- stream B: theta & phi for subgraph i (waits sim(i-2) = last reader of set)
        if (i >= 2) cudaStreamWaitEvent(sB, evS[i - 2], 0);
        tcgemm<<<dim3(2, 10, 16), 160, DYN_BYTES, sB>>>(
            xh, xl, sSC, Cv,
            wth + i * sCC, wtl + i * sCC, wph + i * sCC, wpl + i * sCC, 0, Cv,
            nullptr, thhS, thlS, phhS, phlS, sSC, Cv,
            bt + (size_t)i * Cv, bp + (size_t)i * Cv, 1.0f, Cv, 8, nullptr);
        cudaEventRecord(evT[i], sB);

        // ---- stream M (high prio): sim -> softmax ----
        cudaStreamWaitEvent(sM, evT[i], 0);
        tcgemm<<<dim3(5, 10, 8), 160, DYN_BYTES, sM>>>(
            thhS, thlS, sSC, Cv,
            phhS, phlS, nullptr, nullptr, sSC, Cv,
            sim, nullptr, nullptr, nullptr, nullptr, sSS, Sv,
            nullptr, nullptr, inv_sqrt, Cv, NOSPLIT, nullptr);
        cudaEventRecord(evS[i], sM);

        // softmax(i) writes ath[set]; tmp(i-2) on C was the last reader of that set
        if (i >= 2) cudaStreamWaitEvent(sM, evTm[i - 2], 0);
        masked_softmax_kernel<<<Bv * Sv, 256, 0, sM>>>(
            sim, athS, atlS, (i == NGv - 1) ? rel : nullptr, owp);
        cudaEventRecord(evSM[i], sM);

        // ---- stream C: tmp -> agg -> finalize (in order; off the critical path) ----
        cudaStreamWaitEvent(sC, evSM[i], 0);
        tcgemm<<<dim3(2, 10, 8), 160, DYN_BYTES, sC>>>(
            athS, atlS, sSS, Sv,
            xth, xtl, nullptr, nullptr, sCS, Sv,
            nullptr, tphS, tplS, nullptr, nullptr, sSC, Cv,
            nullptr, nullptr, 1.0f, Sv, NOSPLIT, nullptr);
        cudaEventRecord(evTm[i], sC);

        tcgemm<<<dim3(2, 10, 8), 160, DYN_BYTES, sC>>>(
            tphS, tplS, sSC, Cv,
            wgh + i * sCC, wgl + i * sCC, nullptr, nullptr, 0, Cv,
            agg, nullptr, nullptr, nullptr, nullptr, sSC, Cv,
            nullptr, nullptr, 1.0f, Cv, NOSPLIT, stats + (size_t)i * Bv * 2);

        finalize_kernel<<<(int)((sSC * Bv + 255) / 256), 256, 0, sC>>>(
            agg, lns + (size_t)i * sSC, lnb + (size_t)i * sSC, out,
            i == 0 ? 1 : 0, stats + (size_t)i * Bv * 2);
        cudaEventRecord(evA[i], sC);
    }

    // join: evA[11] transitively covers sB (thph->sim), sM (sim/softmax) and sC chains
    cudaStreamWaitEvent(0, evA[NGv - 1], 0);

    cudaEventDestroy(evFork);
    for (int i = 0; i < NGv; i++) {
        cudaEventDestroy(evT[i]); cudaEventDestroy(evS[i]); cudaEventDestroy(evSM[i]);
        cudaEventDestroy(evTm[i]); cudaEventDestroy(evA[i]);
    }
    cudaStreamDestroy(sM);
    cudaStreamDestroy(sB);
    cudaStreamDestroy(sC);
}